// round 10
// baseline (speedup 1.0000x reference)
#include <cuda_runtime.h>
#include <math.h>

#define Hdim 2048
#define Sdim 4096
#define NB   4
#define FEAT 7
#define Fdim (Hdim*FEAT)
#define Rdim 64
#define HR   (Hdim*Rdim)

typedef unsigned long long ull;

// ---------------- scratch (device globals; allocations are forbidden) -------
__device__ __align__(16) float g_feats[NB*Fdim];
__device__ __align__(16) float g_rowpart[64*NB*Sdim];
__device__ __align__(16) float g_rowss[NB*Sdim];
__device__ __align__(16) float g_part1[16*NB*1024];
__device__ __align__(16) float g_part2[8*NB*512];
__device__ __align__(16) float g_part3[4*NB*256];
__device__ __align__(16) float g_h1[NB*1024];
__device__ __align__(16) float g_h2[NB*512];
__device__ __align__(16) float g_h3[NB*256];
__device__ __align__(16) float g_U[NB*HR];   // U[b][h][r]
__device__ __align__(16) float g_V[NB*HR];   // V[b][r][h]
__device__ __align__(16) float g_T[2*NB*Sdim*Rdim]; // hs@U, 2 k-split halves
__device__ int g_notI;

// ---------------- f32x2 packed-FMA helpers (FFMA2, PTX-only) ----------------
__device__ __forceinline__ ull dup2(float x){
    ull r; unsigned xi = __float_as_uint(x);
    asm("mov.b64 %0, {%1, %1};" : "=l"(r) : "r"(xi));
    return r;
}
__device__ __forceinline__ ull pack2(float x, float y){
    ull r;
    asm("mov.b64 %0, {%1, %2};" : "=l"(r) : "r"(__float_as_uint(x)), "r"(__float_as_uint(y)));
    return r;
}
__device__ __forceinline__ void fma2(ull& acc, ull a, ull b){
    asm("fma.rn.f32x2 %0, %1, %2, %0;" : "+l"(acc) : "l"(a), "l"(b));
}
__device__ __forceinline__ float2 unp2(ull v){
    unsigned lo, hi;
    asm("mov.b64 {%0, %1}, %2;" : "=r"(lo), "=r"(hi) : "l"(v));
    return make_float2(__uint_as_float(lo), __uint_as_float(hi));
}

// ---------------- init ------------------------------------------------------
__global__ void k_init(){ if (threadIdx.x == 0) g_notI = 0; }

// ---------------- identity check on base_transform --------------------------
__global__ void k_checkI(const float* __restrict__ B){
    size_t i0 = ((size_t)blockIdx.x*256u + threadIdx.x)*8u;
    bool bad = false;
    #pragma unroll
    for (int j=0;j<8;j++){
        size_t i = i0 + j;
        int r = (int)(i >> 11), c = (int)(i & 2047);
        float e = (r==c) ? 1.0f : 0.0f;
        if (B[i] != e) bad = true;
    }
    if (bad) g_notI = 1;
}

// ---------------- per-channel stats + row-norm partials ----------------------
// grid NB*64 blocks (32 channels each), 256 threads (8 warps; lane=channel)
__global__ void k_stats(const float* __restrict__ hs){
    int b  = blockIdx.x >> 6;
    int cb = blockIdx.x & 63;
    int h0 = cb * 32;
    int w = threadIdx.x >> 5, l = threadIdx.x & 31;
    const float* base = hs + ((size_t)b*Sdim)*Hdim + h0 + l;
    float* rp = g_rowpart + (size_t)cb*NB*Sdim + (size_t)b*Sdim;
    float s1=0.f,s2=0.f,s3=0.f,s4=0.f, mx=-INFINITY, mn=INFINITY;
    for (int s=w; s<Sdim; s+=8){
        float x  = base[(size_t)s*Hdim];
        float x2 = x*x;
        s1+=x; s2+=x2; s3+=x2*x; s4+=x2*x2;
        mx = fmaxf(mx,x); mn = fminf(mn,x);
        float r = x2;                      // sum of x^2 over these 32 channels
        #pragma unroll
        for (int o=16;o>0;o>>=1) r += __shfl_xor_sync(0xffffffffu, r, o);
        if (l==0) rp[s] = r;
    }
    __shared__ float sm[6][8][32];
    sm[0][w][l]=s1; sm[1][w][l]=s2; sm[2][w][l]=s3;
    sm[3][w][l]=s4; sm[4][w][l]=mx; sm[5][w][l]=mn;
    __syncthreads();
    if (threadIdx.x < 32){
        s1=0.f;s2=0.f;s3=0.f;s4=0.f;mx=-INFINITY;mn=INFINITY;
        #pragma unroll
        for (int j=0;j<8;j++){
            s1+=sm[0][j][l]; s2+=sm[1][j][l]; s3+=sm[2][j][l]; s4+=sm[3][j][l];
            mx=fmaxf(mx,sm[4][j][l]); mn=fminf(mn,sm[5][j][l]);
        }
        const float Sf = (float)Sdim;
        float mean = s1/Sf, ex2=s2/Sf, ex3=s3/Sf, ex4=s4/Sf;
        float varu = (s2 - Sf*mean*mean)/(Sf-1.0f);     // ddof=1 (torch.std)
        float sd = sqrtf(fmaxf(varu,0.f));
        float m3 = ex3 - 3.f*mean*ex2 + 2.f*mean*mean*mean;
        float m4 = ex4 - 4.f*mean*ex3 + 6.f*mean*mean*ex2 - 3.f*mean*mean*mean*mean;
        float q  = sd*sd;
        float skew = m3/(sd*q + 1e-8f);
        float kurt = m4/(q*q  + 1e-8f) - 3.f;
        int h = h0 + l;
        float* f = g_feats + b*Fdim;
        f[h]        = mean;
        f[Hdim+h]   = sd;
        f[3*Hdim+h] = mx;
        f[4*Hdim+h] = mn;
        f[5*Hdim+h] = skew;
        f[6*Hdim+h] = kurt;
    }
}

// reduce 64 channel-block partials -> row L2 norm per (b,s)
__global__ void k_rowred(){
    int tg = blockIdx.x*256 + threadIdx.x;   // 0..16383
    int b = tg >> 12, s = tg & 4095;
    float r = 0.f;
    #pragma unroll 8
    for (int cb=0; cb<64; cb++)
        r += g_rowpart[(size_t)cb*NB*Sdim + (size_t)b*Sdim + s];
    g_rowss[b*Sdim + s] = sqrtf(r);
}

// mean over S of row norms -> broadcast to feats[2H..3H)
__global__ void k_rowmean(){
    int b = blockIdx.x, t = threadIdx.x;
    float p = 0.f;
    for (int s=t; s<Sdim; s+=256) p += g_rowss[b*Sdim+s];
    __shared__ float sm[256];
    sm[t]=p; __syncthreads();
    for (int o=128;o>0;o>>=1){ if(t<o) sm[t]+=sm[t+o]; __syncthreads(); }
    float nrm = sm[0]/(float)Sdim;
    for (int h=t; h<Hdim; h+=256) g_feats[b*Fdim + 2*Hdim + h] = nrm;
}

// ---------------- small FC layer, k-split partials ---------------------------
// grid (ncols/128, nparts), 128 threads; Kin = kchunk*gridDim.y
__global__ void k_fcpart(const float* __restrict__ in, int kchunk,
                         const float* __restrict__ W, int ncols,
                         float* __restrict__ parts){
    __shared__ float sf[4*896];
    int t = threadIdx.x;
    int c  = blockIdx.x*128 + t;
    int ks = blockIdx.y;
    int k0 = ks*kchunk;
    int Kin = kchunk*gridDim.y;
    int cnt = 4*kchunk;
    for (int i=t;i<cnt;i+=128){
        int b = i/kchunk, k = i - b*kchunk;
        sf[i] = in[b*Kin + k0 + k];
    }
    __syncthreads();
    float a0=0.f,a1=0.f,a2=0.f,a3=0.f;
    const float* Wp = W + (size_t)k0*ncols + c;
    #pragma unroll 4
    for (int k=0;k<kchunk;k++){
        float w = Wp[(size_t)k*ncols];
        a0 += sf[k]*w;
        a1 += sf[kchunk+k]*w;
        a2 += sf[2*kchunk+k]*w;
        a3 += sf[3*kchunk+k]*w;
    }
    parts[(size_t)(ks*4+0)*ncols + c] = a0;
    parts[(size_t)(ks*4+1)*ncols + c] = a1;
    parts[(size_t)(ks*4+2)*ncols + c] = a2;
    parts[(size_t)(ks*4+3)*ncols + c] = a3;
}

// reduce partials + bias, LayerNorm (ddof=0), ReLU. grid NB, 256 threads.
__global__ void k_lnrelu(const float* __restrict__ parts, int nparts,
                         const float* __restrict__ bias, const float* __restrict__ g,
                         const float* __restrict__ beta, float* __restrict__ out,
                         int ncols){
    int b = blockIdx.x, t = threadIdx.x;
    int cpt = ncols >> 8;                 // 4 (1024) or 2 (512)
    float v[4];
    float s1=0.f, s2=0.f;
    for (int j=0;j<cpt;j++){
        int c = t + j*256;
        float a = bias[c];
        for (int p=0;p<nparts;p++) a += parts[(size_t)(p*4+b)*ncols + c];
        v[j]=a; s1+=a; s2+=a*a;
    }
    __shared__ float r1[256], r2[256];
    r1[t]=s1; r2[t]=s2; __syncthreads();
    for (int o=128;o>0;o>>=1){ if(t<o){r1[t]+=r1[t+o]; r2[t]+=r2[t+o];} __syncthreads(); }
    float mean = r1[0]/(float)ncols;
    float var  = r2[0]/(float)ncols - mean*mean;
    float rstd = rsqrtf(var + 1e-5f);
    for (int j=0;j<cpt;j++){
        int c = t + j*256;
        float y = (v[j]-mean)*rstd*g[c] + beta[c];
        out[b*ncols + c] = fmaxf(y, 0.f);
    }
}

// final MLP layer: reduce + bias + ReLU -> g_h3[4][256]
__global__ void k_act3(const float* __restrict__ b3){
    int c = threadIdx.x;
    #pragma unroll
    for (int b=0;b<4;b++){
        float a = b3[c];
        #pragma unroll
        for (int p=0;p<4;p++) a += g_part3[(p*4+b)*256 + c];
        g_h3[b*256+c] = fmaxf(a, 0.f);
    }
}

// ---------------- U / V generation (memory-bound, FFMA2) ---------------------
// grid (256, 2): x = 512-col block, y: 0=U, 1=V. 256 threads, 2 cols each.
__global__ void k_uvgen(const float* __restrict__ Wu, const float* __restrict__ bu,
                        const float* __restrict__ Wv, const float* __restrict__ bv,
                        const float* __restrict__ su, const float* __restrict__ sv){
    __shared__ ull hd[4][256];
    int t = threadIdx.x;
    int m = blockIdx.y;
    const float* W    = m ? Wv : Wu;
    const float* bias = m ? bv : bu;
    float scale       = m ? sv[0] : su[0];
    float* out        = m ? g_V : g_U;
    for (int i=t;i<1024;i+=256) hd[i>>8][i&255] = dup2(g_h3[i]);
    __syncthreads();
    size_t j0 = (size_t)blockIdx.x*512 + t*2;
    ull bz = pack2(bias[j0], bias[j0+1]);
    ull a0=bz, a1=bz, a2=bz, a3=bz;
    const ull* Wp = (const ull*)(W + j0);
    #pragma unroll 4
    for (int k=0;k<256;k++){
        ull w2 = Wp[(size_t)k*(HR/2)];
        fma2(a0, hd[0][k], w2);
        fma2(a1, hd[1][k], w2);
        fma2(a2, hd[2][k], w2);
        fma2(a3, hd[3][k], w2);
    }
    float2 r;
    r = unp2(a0); r.x*=scale; r.y*=scale; *(float2*)&out[(size_t)0*HR + j0] = r;
    r = unp2(a1); r.x*=scale; r.y*=scale; *(float2*)&out[(size_t)1*HR + j0] = r;
    r = unp2(a2); r.x*=scale; r.y*=scale; *(float2*)&out[(size_t)2*HR + j0] = r;
    r = unp2(a3); r.x*=scale; r.y*=scale; *(float2*)&out[(size_t)3*HR + j0] = r;
}

// ---------------- T = hs @ U : [4,4096,64], k-split 2 ------------------------
// grid (16 rowblocks, NB, 2 ksplit), 256 threads, block tile 256x64
__global__ void __launch_bounds__(256) k_tgemm(const float* __restrict__ hs){
    __shared__ ull   hsd[16][256];       // hs values pre-duplicated as f32x2
    __shared__ __align__(16) float Us[16][64];
    int t  = threadIdx.x;
    int tx = t & 7, ty = t >> 3;         // 8 col-groups x 32 row-groups
    int s0 = blockIdx.x*256;
    int b  = blockIdx.y;
    int k0 = blockIdx.z*1024;
    const float* hsb = hs + ((size_t)b*Sdim)*Hdim;
    const float* Ub  = g_U + (size_t)b*HR;
    ull acc[8][4];
    #pragma unroll
    for (int i=0;i<8;i++)
        #pragma unroll
        for (int p=0;p<4;p++) acc[i][p]=0ull;
    for (int kc=0; kc<64; kc++){
        int kb = k0 + kc*16;
        const float4* src = (const float4*)(hsb + (size_t)(s0+t)*Hdim + kb);
        #pragma unroll
        for (int q=0;q<4;q++){
            float4 v = src[q];
            hsd[q*4+0][t]=dup2(v.x); hsd[q*4+1][t]=dup2(v.y);
            hsd[q*4+2][t]=dup2(v.z); hsd[q*4+3][t]=dup2(v.w);
        }
        {
            float4 v = ((const float4*)(Ub + (size_t)kb*64))[t];
            int kk = (t*4)>>6, c = (t*4)&63;
            *(float4*)&Us[kk][c] = v;
        }
        __syncthreads();
        #pragma unroll
        for (int k=0;k<16;k++){
            ull u[4], h[8];
            #pragma unroll
            for (int p=0;p<4;p++) u[p] = *(const ull*)&Us[k][tx*8 + p*2];
            #pragma unroll
            for (int i=0;i<8;i++) h[i] = hsd[k][ty*8+i];
            #pragma unroll
            for (int i=0;i<8;i++)
                #pragma unroll
                for (int p=0;p<4;p++) fma2(acc[i][p], h[i], u[p]);
        }
        __syncthreads();
    }
    float* Tp = g_T + ((size_t)(blockIdx.z*NB + b)*Sdim)*Rdim;
    #pragma unroll
    for (int i=0;i<8;i++){
        size_t s = s0 + ty*8 + i;
        #pragma unroll
        for (int p=0;p<4;p++)
            *(ull*)&Tp[s*64 + tx*8 + p*2] = acc[i][p];
    }
}

// ---------------- out = rw*hs + (1-rw)*(T @ V) -------------------------------
// grid (16 colblocks, 32 rowblocks, NB), 256 threads, tile 128x128, K=64
__global__ void __launch_bounds__(256) k_epilogue(const float* __restrict__ hs,
                        float* __restrict__ out, const float* __restrict__ rwp){
    __shared__ ull   Td[16][128];
    __shared__ __align__(16) float Vs[16][128];
    int t  = threadIdx.x;
    int tx = t & 15, ty = t >> 4;        // 16 col-groups x 16 row-groups
    int h0 = blockIdx.x*128;
    int s0 = blockIdx.y*128;
    int b  = blockIdx.z;
    const float* Vb = g_V + (size_t)b*HR;
    const float* T0 = g_T + ((size_t)b*Sdim)*Rdim;
    const float* T1 = g_T + ((size_t)(NB + b)*Sdim)*Rdim;
    ull acc[8][4];
    #pragma unroll
    for (int i=0;i<8;i++)
        #pragma unroll
        for (int p=0;p<4;p++) acc[i][p]=0ull;
    for (int kc=0; kc<4; kc++){
        int k0 = kc*16;
        {   // stage T (sum the two k-split halves, duplicate as f32x2)
            int m = t>>1, seg = (t&1)*8;
            size_t off = (size_t)(s0+m)*64 + k0 + seg;
            float4 a0 = *(const float4*)(T0+off);
            float4 a1 = *(const float4*)(T0+off+4);
            float4 c0 = *(const float4*)(T1+off);
            float4 c1 = *(const float4*)(T1+off+4);
            Td[seg+0][m]=dup2(a0.x+c0.x); Td[seg+1][m]=dup2(a0.y+c0.y);
            Td[seg+2][m]=dup2(a0.z+c0.z); Td[seg+3][m]=dup2(a0.w+c0.w);
            Td[seg+4][m]=dup2(a1.x+c1.x); Td[seg+5][m]=dup2(a1.y+c1.y);
            Td[seg+6][m]=dup2(a1.z+c1.z); Td[seg+7][m]=dup2(a1.w+c1.w);
        }
        {   // stage V
            int kk = t>>4, c = (t&15)*8;
            const float4* vsrc = (const float4*)(Vb + (size_t)(k0+kk)*Hdim + h0 + c);
            float4 v0 = vsrc[0], v1 = vsrc[1];
            *(float4*)&Vs[kk][c]   = v0;
            *(float4*)&Vs[kk][c+4] = v1;
        }
        __syncthreads();
        #pragma unroll
        for (int k=0;k<16;k++){
            ull u[4], h[8];
            #pragma unroll
            for (int p=0;p<4;p++) u[p] = *(const ull*)&Vs[k][tx*2 + p*32];
            #pragma unroll
            for (int i=0;i<8;i++) h[i] = Td[k][ty*8+i];
            #pragma unroll
            for (int i=0;i<8;i++)
                #pragma unroll
                for (int p=0;p<4;p++) fma2(acc[i][p], h[i], u[p]);
        }
        __syncthreads();
    }
    float rw = rwp[0];
    float cw = 1.0f - rw;
    float rh = (g_notI==0) ? rw : 0.0f;  // identity residual fused; else fallback adds it
    #pragma unroll
    for (int i=0;i<8;i++){
        size_t rowoff = ((size_t)b*Sdim + s0 + ty*8 + i)*Hdim + h0;
        #pragma unroll
        for (int p=0;p<4;p++){
            int h = tx*2 + p*32;
            float2 a = unp2(acc[i][p]);
            float2 x = *(const float2*)(hs + rowoff + h);
            float2 o;
            o.x = cw*a.x + rh*x.x;
            o.y = cw*a.y + rh*x.y;
            *(float2*)(out + rowoff + h) = o;
        }
    }
}

// ---------------- fallback: out += rw * hs @ base (non-identity base only) ---
__global__ void k_fallback(const float* __restrict__ hs, const float* __restrict__ B,
                           float* __restrict__ out, const float* __restrict__ rwp){
    if (g_notI == 0) return;
    __shared__ float row[Hdim];
    int t = threadIdx.x;
    float rw = rwp[0];
    for (int r=0;r<8;r++){
        int rid = blockIdx.x*8 + r;           // 0..16383
        int b = rid >> 12, s = rid & 4095;
        const float* src = hs + ((size_t)b*Sdim + s)*Hdim;
        __syncthreads();
        for (int i=t;i<Hdim;i+=256) row[i]=src[i];
        __syncthreads();
        for (int j=0;j<8;j++){
            int h = t + j*256;
            float a = 0.f;
            for (int k=0;k<Hdim;k++) a += row[k]*B[(size_t)k*Hdim + h];
            out[((size_t)b*Sdim + s)*Hdim + h] += rw*a;
        }
    }
}

// ---------------- launch -----------------------------------------------------
extern "C" void kernel_launch(void* const* d_in, const int* in_sizes, int n_in,
                              void* d_out, int out_size){
    const float* hs = (const float*)d_in[0];
    const float* W1 = (const float*)d_in[1];
    const float* b1 = (const float*)d_in[2];
    const float* g1 = (const float*)d_in[3];
    const float* be1= (const float*)d_in[4];
    const float* W2 = (const float*)d_in[5];
    const float* b2 = (const float*)d_in[6];
    const float* g2 = (const float*)d_in[7];
    const float* be2= (const float*)d_in[8];
    const float* W3 = (const float*)d_in[9];
    const float* b3 = (const float*)d_in[10];
    const float* Wu = (const float*)d_in[11];
    const float* bu = (const float*)d_in[12];
    const float* Wv = (const float*)d_in[13];
    const float* bv = (const float*)d_in[14];
    const float* su = (const float*)d_in[15];
    const float* sv = (const float*)d_in[16];
    const float* rw = (const float*)d_in[17];
    const float* Bt = (const float*)d_in[18];
    float* out = (float*)d_out;

    void *p_feats=0,*p_p1=0,*p_p2=0,*p_p3=0,*p_h1=0,*p_h2=0;
    cudaGetSymbolAddress(&p_feats, g_feats);
    cudaGetSymbolAddress(&p_p1, g_part1);
    cudaGetSymbolAddress(&p_p2, g_part2);
    cudaGetSymbolAddress(&p_p3, g_part3);
    cudaGetSymbolAddress(&p_h1, g_h1);
    cudaGetSymbolAddress(&p_h2, g_h2);

    k_init   <<<1,1>>>();
    k_checkI <<<2048,256>>>(Bt);
    k_stats  <<<NB*64,256>>>(hs);
    k_rowred <<<64,256>>>();
    k_rowmean<<<NB,256>>>();
    k_fcpart <<<dim3(8,16),128>>>((const float*)p_feats, 896, W1, 1024, (float*)p_p1);
    k_lnrelu <<<NB,256>>>((const float*)p_p1, 16, b1, g1, be1, (float*)p_h1, 1024);
    k_fcpart <<<dim3(4,8),128>>>((const float*)p_h1, 128, W2, 512, (float*)p_p2);
    k_lnrelu <<<NB,256>>>((const float*)p_p2, 8, b2, g2, be2, (float*)p_h2, 512);
    k_fcpart <<<dim3(2,4),128>>>((const float*)p_h2, 128, W3, 256, (float*)p_p3);
    k_act3   <<<1,256>>>(b3);
    k_uvgen  <<<dim3(256,2),256>>>(Wu, bu, Wv, bv, su, sv);
    k_tgemm  <<<dim3(16,NB,2),256>>>(hs);
    k_epilogue<<<dim3(16,32,NB),256>>>(hs, out, rw);
    k_fallback<<<2048,256>>>(hs, Bt, out, rw);
}

// round 13
// speedup vs baseline: 1.5195x; 1.5195x over previous
#include <cuda_runtime.h>
#include <math.h>

#define Hdim 2048
#define Sdim 4096
#define NB   4
#define FEAT 7
#define Fdim (Hdim*FEAT)
#define Rdim 64
#define HR   (Hdim*Rdim)
#define RS   32   // row splits in k_stats

typedef unsigned long long ull;

// ---------------- scratch (device globals; allocations are forbidden) -------
__device__ __align__(16) float g_feats[NB*Fdim];
__device__ __align__(16) float g_spart[RS*NB*6*Hdim];   // per-rowsplit moment partials
__device__ __align__(16) float g_rowpart[16*NB*Sdim];
__device__ __align__(16) float g_rowss[NB*Sdim];
__device__ __align__(16) float g_part1[32*NB*1024];
__device__ __align__(16) float g_part2[16*NB*512];
__device__ __align__(16) float g_part3[8*NB*256];
__device__ __align__(16) float g_h1[NB*1024];
__device__ __align__(16) float g_h2[NB*512];
__device__ __align__(16) float g_h3[NB*256];
__device__ __align__(16) float g_U[NB*HR];   // U[b][h][r]
__device__ __align__(16) float g_V[NB*HR];   // V[b][r][h]
__device__ __align__(16) float g_T[2*NB*Sdim*Rdim]; // hs@U, 2 k-split halves
__device__ int g_notI;

// ---------------- f32x2 packed-FMA helpers (FFMA2, PTX-only) ----------------
__device__ __forceinline__ ull dup2(float x){
    ull r; unsigned xi = __float_as_uint(x);
    asm("mov.b64 %0, {%1, %1};" : "=l"(r) : "r"(xi));
    return r;
}
__device__ __forceinline__ ull pack2(float x, float y){
    ull r;
    asm("mov.b64 %0, {%1, %2};" : "=l"(r) : "r"(__float_as_uint(x)), "r"(__float_as_uint(y)));
    return r;
}
__device__ __forceinline__ void fma2(ull& acc, ull a, ull b){
    asm("fma.rn.f32x2 %0, %1, %2, %0;" : "+l"(acc) : "l"(a), "l"(b));
}
__device__ __forceinline__ float2 unp2(ull v){
    unsigned lo, hi;
    asm("mov.b64 {%0, %1}, %2;" : "=r"(lo), "=r"(hi) : "l"(v));
    return make_float2(__uint_as_float(lo), __uint_as_float(hi));
}

// ---------------- init ------------------------------------------------------
__global__ void k_init(){ if (threadIdx.x == 0) g_notI = 0; }

// ---------------- identity check on base_transform --------------------------
__global__ void k_checkI(const float* __restrict__ B){
    size_t i0 = ((size_t)blockIdx.x*256u + threadIdx.x)*8u;
    bool bad = false;
    #pragma unroll
    for (int j=0;j<8;j++){
        size_t i = i0 + j;
        int r = (int)(i >> 11), c = (int)(i & 2047);
        float e = (r==c) ? 1.0f : 0.0f;
        if (B[i] != e) bad = true;
    }
    if (bad) g_notI = 1;
}

// ---------------- per-channel moment partials + row-norm partials ------------
// grid (2 slabs, RS rowsplits, NB), 256 threads; thread owns 4 channels (float4)
__global__ void __launch_bounds__(256) k_stats(const float* __restrict__ hs){
    int cb = blockIdx.x;                 // 1024-channel slab
    int rs = blockIdx.y;                 // 128-row split
    int b  = blockIdx.z;
    int t = threadIdx.x, w = t>>5, l = t&31;
    int h = cb*1024 + t*4;
    const float* rowbase = hs + (size_t)b*Sdim*Hdim + h;
    float* rp = g_rowpart + (size_t)(cb*8+w)*NB*Sdim + (size_t)b*Sdim;
    float4 s1={0,0,0,0}, s2=s1, s3=s1, s4=s1;
    float4 mx={-INFINITY,-INFINITY,-INFINITY,-INFINITY};
    float4 mn={ INFINITY, INFINITY, INFINITY, INFINITY};
    int s0 = rs*(Sdim/RS);
    #pragma unroll 4
    for (int i=0;i<Sdim/RS;i++){
        int s = s0 + i;
        float4 v = *(const float4*)(rowbase + (size_t)s*Hdim);
        #define ACC(c) { float x=v.c; float x2=x*x; s1.c+=x; s2.c+=x2; s3.c+=x2*x; s4.c+=x2*x2; \
                         mx.c=fmaxf(mx.c,x); mn.c=fminf(mn.c,x); }
        ACC(x) ACC(y) ACC(z) ACC(w)
        #undef ACC
        float r = v.x*v.x + v.y*v.y + v.z*v.z + v.w*v.w;   // 128-channel warp sum below
        #pragma unroll
        for (int o=16;o>0;o>>=1) r += __shfl_xor_sync(0xffffffffu, r, o);
        if (l==0) rp[s] = r;
    }
    size_t spb = ((size_t)(rs*NB + b))*6*Hdim + h;
    *(float4*)(g_spart + spb + 0*(size_t)Hdim) = s1;
    *(float4*)(g_spart + spb + 1*(size_t)Hdim) = s2;
    *(float4*)(g_spart + spb + 2*(size_t)Hdim) = s3;
    *(float4*)(g_spart + spb + 3*(size_t)Hdim) = s4;
    *(float4*)(g_spart + spb + 4*(size_t)Hdim) = mx;
    *(float4*)(g_spart + spb + 5*(size_t)Hdim) = mn;
}

// combine RS moment partials -> per-channel stats. grid (Hdim/256, NB), 256 thr
__global__ void k_statfin(){
    int b = blockIdx.y;
    int h = blockIdx.x*256 + threadIdx.x;
    float s1=0.f,s2=0.f,s3=0.f,s4=0.f, mx=-INFINITY, mn=INFINITY;
    #pragma unroll 4
    for (int r=0;r<RS;r++){
        size_t base = ((size_t)(r*NB+b))*6*Hdim + h;
        s1 += g_spart[base];
        s2 += g_spart[base +   (size_t)Hdim];
        s3 += g_spart[base + 2*(size_t)Hdim];
        s4 += g_spart[base + 3*(size_t)Hdim];
        mx = fmaxf(mx, g_spart[base + 4*(size_t)Hdim]);
        mn = fminf(mn, g_spart[base + 5*(size_t)Hdim]);
    }
    const float Sf = (float)Sdim;
    float mean = s1/Sf, ex2=s2/Sf, ex3=s3/Sf, ex4=s4/Sf;
    float varu = (s2 - Sf*mean*mean)/(Sf-1.0f);     // ddof=1 (torch.std)
    float sd = sqrtf(fmaxf(varu,0.f));
    float m3 = ex3 - 3.f*mean*ex2 + 2.f*mean*mean*mean;
    float m4 = ex4 - 4.f*mean*ex3 + 6.f*mean*mean*ex2 - 3.f*mean*mean*mean*mean;
    float q  = sd*sd;
    float skew = m3/(sd*q + 1e-8f);
    float kurt = m4/(q*q  + 1e-8f) - 3.f;
    float* f = g_feats + b*Fdim;
    f[h]        = mean;
    f[Hdim+h]   = sd;
    f[3*Hdim+h] = mx;
    f[4*Hdim+h] = mn;
    f[5*Hdim+h] = skew;
    f[6*Hdim+h] = kurt;
}

// reduce 16 warp partials -> row L2 norm per (b,s)
__global__ void k_rowred(){
    int tg = blockIdx.x*256 + threadIdx.x;   // 0..16383
    int b = tg >> 12, s = tg & 4095;
    float r = 0.f;
    #pragma unroll
    for (int cb=0; cb<16; cb++)
        r += g_rowpart[(size_t)cb*NB*Sdim + (size_t)b*Sdim + s];
    g_rowss[b*Sdim + s] = sqrtf(r);
}

// mean over S of row norms -> broadcast to feats[2H..3H)
__global__ void k_rowmean(){
    int b = blockIdx.x, t = threadIdx.x;
    float p = 0.f;
    for (int s=t; s<Sdim; s+=256) p += g_rowss[b*Sdim+s];
    __shared__ float sm[256];
    sm[t]=p; __syncthreads();
    for (int o=128;o>0;o>>=1){ if(t<o) sm[t]+=sm[t+o]; __syncthreads(); }
    float nrm = sm[0]/(float)Sdim;
    for (int h=t; h<Hdim; h+=256) g_feats[b*Fdim + 2*Hdim + h] = nrm;
}

// ---------------- small FC layer, k-split partials ---------------------------
// grid (ncols/128, nparts), 128 threads; Kin = kchunk*gridDim.y
__global__ void k_fcpart(const float* __restrict__ in, int kchunk,
                         const float* __restrict__ W, int ncols,
                         float* __restrict__ parts){
    __shared__ float sf[4*896];
    int t = threadIdx.x;
    int c  = blockIdx.x*128 + t;
    int ks = blockIdx.y;
    int k0 = ks*kchunk;
    int Kin = kchunk*gridDim.y;
    int cnt = 4*kchunk;
    for (int i=t;i<cnt;i+=128){
        int b = i/kchunk, k = i - b*kchunk;
        sf[i] = in[b*Kin + k0 + k];
    }
    __syncthreads();
    float a0=0.f,a1=0.f,a2=0.f,a3=0.f;
    const float* Wp = W + (size_t)k0*ncols + c;
    #pragma unroll 8
    for (int k=0;k<kchunk;k++){
        float w = Wp[(size_t)k*ncols];
        a0 += sf[k]*w;
        a1 += sf[kchunk+k]*w;
        a2 += sf[2*kchunk+k]*w;
        a3 += sf[3*kchunk+k]*w;
    }
    parts[(size_t)(ks*4+0)*ncols + c] = a0;
    parts[(size_t)(ks*4+1)*ncols + c] = a1;
    parts[(size_t)(ks*4+2)*ncols + c] = a2;
    parts[(size_t)(ks*4+3)*ncols + c] = a3;
}

// reduce partials + bias, LayerNorm (ddof=0), ReLU. grid NB, 256 threads.
__global__ void k_lnrelu(const float* __restrict__ parts, int nparts,
                         const float* __restrict__ bias, const float* __restrict__ g,
                         const float* __restrict__ beta, float* __restrict__ out,
                         int ncols){
    int b = blockIdx.x, t = threadIdx.x;
    int cpt = ncols >> 8;                 // 4 (1024) or 2 (512)
    float v[4];
    float s1=0.f, s2=0.f;
    for (int j=0;j<cpt;j++){
        int c = t + j*256;
        float a = bias[c];
        for (int p=0;p<nparts;p++) a += parts[(size_t)(p*4+b)*ncols + c];
        v[j]=a; s1+=a; s2+=a*a;
    }
    __shared__ float r1[256], r2[256];
    r1[t]=s1; r2[t]=s2; __syncthreads();
    for (int o=128;o>0;o>>=1){ if(t<o){r1[t]+=r1[t+o]; r2[t]+=r2[t+o];} __syncthreads(); }
    float mean = r1[0]/(float)ncols;
    float var  = r2[0]/(float)ncols - mean*mean;
    float rstd = rsqrtf(var + 1e-5f);
    for (int j=0;j<cpt;j++){
        int c = t + j*256;
        float y = (v[j]-mean)*rstd*g[c] + beta[c];
        out[b*ncols + c] = fmaxf(y, 0.f);
    }
}

// final MLP layer: reduce + bias + ReLU -> g_h3[4][256]
__global__ void k_act3(const float* __restrict__ b3){
    int c = threadIdx.x;
    #pragma unroll
    for (int b=0;b<4;b++){
        float a = b3[c];
        #pragma unroll
        for (int p=0;p<8;p++) a += g_part3[(p*4+b)*256 + c];
        g_h3[b*256+c] = fmaxf(a, 0.f);
    }
}

// ---------------- U / V generation (memory-bound, FFMA2) ---------------------
// grid (256, 2): x = 512-col block, y: 0=U, 1=V. 256 threads, 2 cols each.
__global__ void k_uvgen(const float* __restrict__ Wu, const float* __restrict__ bu,
                        const float* __restrict__ Wv, const float* __restrict__ bv,
                        const float* __restrict__ su, const float* __restrict__ sv){
    __shared__ ull hd[4][256];
    int t = threadIdx.x;
    int m = blockIdx.y;
    const float* W    = m ? Wv : Wu;
    const float* bias = m ? bv : bu;
    float scale       = m ? sv[0] : su[0];
    float* out        = m ? g_V : g_U;
    for (int i=t;i<1024;i+=256) hd[i>>8][i&255] = dup2(g_h3[i]);
    __syncthreads();
    size_t j0 = (size_t)blockIdx.x*512 + t*2;
    ull bz = pack2(bias[j0], bias[j0+1]);
    ull a0=bz, a1=bz, a2=bz, a3=bz;
    const ull* Wp = (const ull*)(W + j0);
    #pragma unroll 8
    for (int k=0;k<256;k++){
        ull w2 = Wp[(size_t)k*(HR/2)];
        fma2(a0, hd[0][k], w2);
        fma2(a1, hd[1][k], w2);
        fma2(a2, hd[2][k], w2);
        fma2(a3, hd[3][k], w2);
    }
    float2 r;
    r = unp2(a0); r.x*=scale; r.y*=scale; *(float2*)&out[(size_t)0*HR + j0] = r;
    r = unp2(a1); r.x*=scale; r.y*=scale; *(float2*)&out[(size_t)1*HR + j0] = r;
    r = unp2(a2); r.x*=scale; r.y*=scale; *(float2*)&out[(size_t)2*HR + j0] = r;
    r = unp2(a3); r.x*=scale; r.y*=scale; *(float2*)&out[(size_t)3*HR + j0] = r;
}

// ---------------- T = hs @ U : [4,4096,64], k-split 2 ------------------------
// grid (16 rowblocks, NB, 2 ksplit), 256 threads, block tile 256x64
__global__ void __launch_bounds__(256) k_tgemm(const float* __restrict__ hs){
    __shared__ ull   hsd[16][256];       // hs values pre-duplicated as f32x2
    __shared__ __align__(16) float Us[16][64];
    int t  = threadIdx.x;
    int tx = t & 7, ty = t >> 3;         // 8 col-groups x 32 row-groups
    int s0 = blockIdx.x*256;
    int b  = blockIdx.y;
    int k0 = blockIdx.z*1024;
    const float* hsb = hs + ((size_t)b*Sdim)*Hdim;
    const float* Ub  = g_U + (size_t)b*HR;
    ull acc[8][4];
    #pragma unroll
    for (int i=0;i<8;i++)
        #pragma unroll
        for (int p=0;p<4;p++) acc[i][p]=0ull;
    for (int kc=0; kc<64; kc++){
        int kb = k0 + kc*16;
        const float4* src = (const float4*)(hsb + (size_t)(s0+t)*Hdim + kb);
        #pragma unroll
        for (int q=0;q<4;q++){
            float4 v = src[q];
            hsd[q*4+0][t]=dup2(v.x); hsd[q*4+1][t]=dup2(v.y);
            hsd[q*4+2][t]=dup2(v.z); hsd[q*4+3][t]=dup2(v.w);
        }
        {
            float4 v = ((const float4*)(Ub + (size_t)kb*64))[t];
            int kk = (t*4)>>6, c = (t*4)&63;
            *(float4*)&Us[kk][c] = v;
        }
        __syncthreads();
        #pragma unroll
        for (int k=0;k<16;k++){
            ull u[4], h[8];
            #pragma unroll
            for (int p=0;p<4;p++) u[p] = *(const ull*)&Us[k][tx*8 + p*2];
            #pragma unroll
            for (int i=0;i<8;i++) h[i] = hsd[k][ty*8+i];
            #pragma unroll
            for (int i=0;i<8;i++)
                #pragma unroll
                for (int p=0;p<4;p++) fma2(acc[i][p], h[i], u[p]);
        }
        __syncthreads();
    }
    float* Tp = g_T + ((size_t)(blockIdx.z*NB + b)*Sdim)*Rdim;
    #pragma unroll
    for (int i=0;i<8;i++){
        size_t s = s0 + ty*8 + i;
        #pragma unroll
        for (int p=0;p<4;p++)
            *(ull*)&Tp[s*64 + tx*8 + p*2] = acc[i][p];
    }
}

// ---------------- out = rw*hs + (1-rw)*(T @ V) -------------------------------
// grid (16 colblocks, 32 rowblocks, NB), 256 threads, tile 128x128, K=64
__global__ void __launch_bounds__(256) k_epilogue(const float* __restrict__ hs,
                        float* __restrict__ out, const float* __restrict__ rwp){
    __shared__ ull   Td[16][128];
    __shared__ __align__(16) float Vs[16][128];
    int t  = threadIdx.x;
    int tx = t & 15, ty = t >> 4;        // 16 col-groups x 16 row-groups
    int h0 = blockIdx.x*128;
    int s0 = blockIdx.y*128;
    int b  = blockIdx.z;
    const float* Vb = g_V + (size_t)b*HR;
    const float* T0 = g_T + ((size_t)b*Sdim)*Rdim;
    const float* T1 = g_T + ((size_t)(NB + b)*Sdim)*Rdim;
    ull acc[8][4];
    #pragma unroll
    for (int i=0;i<8;i++)
        #pragma unroll
        for (int p=0;p<4;p++) acc[i][p]=0ull;
    for (int kc=0; kc<4; kc++){
        int k0 = kc*16;
        {   // stage T (sum the two k-split halves, duplicate as f32x2)
            int m = t>>1, seg = (t&1)*8;
            size_t off = (size_t)(s0+m)*64 + k0 + seg;
            float4 a0 = *(const float4*)(T0+off);
            float4 a1 = *(const float4*)(T0+off+4);
            float4 c0 = *(const float4*)(T1+off);
            float4 c1 = *(const float4*)(T1+off+4);
            Td[seg+0][m]=dup2(a0.x+c0.x); Td[seg+1][m]=dup2(a0.y+c0.y);
            Td[seg+2][m]=dup2(a0.z+c0.z); Td[seg+3][m]=dup2(a0.w+c0.w);
            Td[seg+4][m]=dup2(a1.x+c1.x); Td[seg+5][m]=dup2(a1.y+c1.y);
            Td[seg+6][m]=dup2(a1.z+c1.z); Td[seg+7][m]=dup2(a1.w+c1.w);
        }
        {   // stage V
            int kk = t>>4, c = (t&15)*8;
            const float4* vsrc = (const float4*)(Vb + (size_t)(k0+kk)*Hdim + h0 + c);
            float4 v0 = vsrc[0], v1 = vsrc[1];
            *(float4*)&Vs[kk][c]   = v0;
            *(float4*)&Vs[kk][c+4] = v1;
        }
        __syncthreads();
        #pragma unroll
        for (int k=0;k<16;k++){
            ull u[4], h[8];
            #pragma unroll
            for (int p=0;p<4;p++) u[p] = *(const ull*)&Vs[k][tx*2 + p*32];
            #pragma unroll
            for (int i=0;i<8;i++) h[i] = Td[k][ty*8+i];
            #pragma unroll
            for (int i=0;i<8;i++)
                #pragma unroll
                for (int p=0;p<4;p++) fma2(acc[i][p], h[i], u[p]);
        }
        __syncthreads();
    }
    float rw = rwp[0];
    float cw = 1.0f - rw;
    float rh = (g_notI==0) ? rw : 0.0f;  // identity residual fused; else fallback adds it
    #pragma unroll
    for (int i=0;i<8;i++){
        size_t rowoff = ((size_t)b*Sdim + s0 + ty*8 + i)*Hdim + h0;
        #pragma unroll
        for (int p=0;p<4;p++){
            int h = tx*2 + p*32;
            float2 a = unp2(acc[i][p]);
            float2 x = *(const float2*)(hs + rowoff + h);
            float2 o;
            o.x = cw*a.x + rh*x.x;
            o.y = cw*a.y + rh*x.y;
            *(float2*)(out + rowoff + h) = o;
        }
    }
}

// ---------------- fallback: out += rw * hs @ base (non-identity base only) ---
__global__ void k_fallback(const float* __restrict__ hs, const float* __restrict__ B,
                           float* __restrict__ out, const float* __restrict__ rwp){
    if (g_notI == 0) return;
    __shared__ float row[Hdim];
    int t = threadIdx.x;
    float rw = rwp[0];
    for (int r=0;r<8;r++){
        int rid = blockIdx.x*8 + r;           // 0..16383
        int b = rid >> 12, s = rid & 4095;
        const float* src = hs + ((size_t)b*Sdim + s)*Hdim;
        __syncthreads();
        for (int i=t;i<Hdim;i+=256) row[i]=src[i];
        __syncthreads();
        for (int j=0;j<8;j++){
            int h = t + j*256;
            float a = 0.f;
            for (int k=0;k<Hdim;k++) a += row[k]*B[(size_t)k*Hdim + h];
            out[((size_t)b*Sdim + s)*Hdim + h] += rw*a;
        }
    }
}

// ---------------- launch -----------------------------------------------------
extern "C" void kernel_launch(void* const* d_in, const int* in_sizes, int n_in,
                              void* d_out, int out_size){
    const float* hs = (const float*)d_in[0];
    const float* W1 = (const float*)d_in[1];
    const float* b1 = (const float*)d_in[2];
    const float* g1 = (const float*)d_in[3];
    const float* be1= (const float*)d_in[4];
    const float* W2 = (const float*)d_in[5];
    const float* b2 = (const float*)d_in[6];
    const float* g2 = (const float*)d_in[7];
    const float* be2= (const float*)d_in[8];
    const float* W3 = (const float*)d_in[9];
    const float* b3 = (const float*)d_in[10];
    const float* Wu = (const float*)d_in[11];
    const float* bu = (const float*)d_in[12];
    const float* Wv = (const float*)d_in[13];
    const float* bv = (const float*)d_in[14];
    const float* su = (const float*)d_in[15];
    const float* sv = (const float*)d_in[16];
    const float* rw = (const float*)d_in[17];
    const float* Bt = (const float*)d_in[18];
    float* out = (float*)d_out;

    void *p_feats=0,*p_p1=0,*p_p2=0,*p_p3=0,*p_h1=0,*p_h2=0;
    cudaGetSymbolAddress(&p_feats, g_feats);
    cudaGetSymbolAddress(&p_p1, g_part1);
    cudaGetSymbolAddress(&p_p2, g_part2);
    cudaGetSymbolAddress(&p_p3, g_part3);
    cudaGetSymbolAddress(&p_h1, g_h1);
    cudaGetSymbolAddress(&p_h2, g_h2);

    k_init   <<<1,1>>>();
    k_checkI <<<2048,256>>>(Bt);
    k_stats  <<<dim3(2,RS,NB),256>>>(hs);
    k_statfin<<<dim3(Hdim/256,NB),256>>>();
    k_rowred <<<64,256>>>();
    k_rowmean<<<NB,256>>>();
    k_fcpart <<<dim3(8,32),128>>>((const float*)p_feats, 448, W1, 1024, (float*)p_p1);
    k_lnrelu <<<NB,256>>>((const float*)p_p1, 32, b1, g1, be1, (float*)p_h1, 1024);
    k_fcpart <<<dim3(4,16),128>>>((const float*)p_h1, 64, W2, 512, (float*)p_p2);
    k_lnrelu <<<NB,256>>>((const float*)p_p2, 16, b2, g2, be2, (float*)p_h2, 512);
    k_fcpart <<<dim3(2,8),128>>>((const float*)p_h2, 64, W3, 256, (float*)p_p3);
    k_act3   <<<1,256>>>(b3);
    k_uvgen  <<<dim3(256,2),256>>>(Wu, bu, Wv, bv, su, sv);
    k_tgemm  <<<dim3(16,NB,2),256>>>(hs);
    k_epilogue<<<dim3(16,32,NB),256>>>(hs, out, rw);
    k_fallback<<<2048,256>>>(hs, Bt, out, rw);
}